// round 6
// baseline (speedup 1.0000x reference)
#include <cuda_runtime.h>

typedef unsigned long long ull;

// film buffer: [b(4)][ch(256)][tc(1024)]
__device__ float g_film[4 * 256 * 1024];

// ---------------- packed f32x2 helpers (sm_103a FFMA2 path) ----------------
__device__ __forceinline__ ull pk2(float lo, float hi) {
    ull r; asm("mov.b64 %0, {%1, %2};" : "=l"(r) : "f"(lo), "f"(hi)); return r;
}
__device__ __forceinline__ void upk2(float& lo, float& hi, ull v) {
    asm("mov.b64 {%0, %1}, %2;" : "=f"(lo), "=f"(hi) : "l"(v));
}
__device__ __forceinline__ ull ffma2(ull a, ull b, ull c) {
    ull d; asm("fma.rn.f32x2 %0, %1, %2, %3;" : "=l"(d) : "l"(a), "l"(b), "l"(c)); return d;
}
__device__ __forceinline__ ull fadd2(ull a, ull b) {
    ull d; asm("add.rn.f32x2 %0, %1, %2;" : "=l"(d) : "l"(a), "l"(b)); return d;
}
__device__ __forceinline__ ull fmul2(ull a, ull b) {
    ull d; asm("mul.rn.f32x2 %0, %1, %2;" : "=l"(d) : "l"(a), "l"(b)); return d;
}

// ===========================================================================
// Kernel 1: control-rate MLP. 128 blocks x 256 threads, 32 positions/block.
// ===========================================================================
__global__ __launch_bounds__(256) void mlp_kernel(
    const float* __restrict__ cein,
    const float* __restrict__ W0, const float* __restrict__ B0,
    const float* __restrict__ G0, const float* __restrict__ Be0,
    const float* __restrict__ W1, const float* __restrict__ B1,
    const float* __restrict__ G1, const float* __restrict__ Be1,
    const float* __restrict__ W2, const float* __restrict__ B2,
    const float* __restrict__ G2, const float* __restrict__ Be2,
    const float* __restrict__ W3, const float* __restrict__ B3)
{
    extern __shared__ float sm1[];
    float* wbuf  = sm1;              // up to 128*257 = 32896 floats
    float* actA  = sm1 + 32896;      // 128 rows x pitch 36
    float* actB  = actA + 4608;
    float* biasS = actB + 4608;      // 256
    float* lngS  = biasS + 256;      // 128
    float* lnbS  = lngS + 128;       // 128
    float* statS = lnbS + 128;       // 64

    const int tid = threadIdx.x;
    const int P0  = blockIdx.x * 32;
    const int b   = P0 >> 10;
    const int tc0 = P0 & 1023;

    // stage input slice actA[c][p] = ce[b][c][tc0+p]
    for (int i = tid; i < 128 * 32; i += 256) {
        int c = i >> 5, p = i & 31;
        actA[c * 36 + p] = cein[(b * 128 + c) * 1024 + tc0 + p];
    }

    const float* Wl[3]  = {W0, W1, W2};
    const float* Bl[3]  = {B0, B1, B2};
    const float* Gl[3]  = {G0, G1, G2};
    const float* Bel[3] = {Be0, Be1, Be2};

    float* ain  = actA;
    float* aout = actB;

    const int o     = tid & 127;
    const int half  = tid >> 7;
    const int pbase = half * 16;
    const int wrp   = tid >> 5;
    const int lane  = tid & 31;

    for (int layer = 0; layer < 3; layer++) {
        __syncthreads();
        // stage transposed weight: wbuf[c*129 + o] = W[o][c]
        const float* W = Wl[layer];
        for (int i = tid; i < 128 * 128; i += 256) {
            int oo = i >> 7, cc = i & 127;
            wbuf[cc * 129 + oo] = W[i];
        }
        if (tid < 128) {
            biasS[tid] = Bl[layer][tid];
            lngS[tid]  = Gl[layer][tid];
            lnbS[tid]  = Bel[layer][tid];
        }
        __syncthreads();

        float acc[16];
        float bo = biasS[o];
#pragma unroll
        for (int p = 0; p < 16; p++) acc[p] = bo;

        const float* arow = ain + pbase;
#pragma unroll 4
        for (int c = 0; c < 128; c++) {
            float w = wbuf[c * 129 + o];
            const float4* hr = (const float4*)(arow + c * 36);
            float4 h0 = hr[0], h1 = hr[1], h2 = hr[2], h3 = hr[3];
            acc[0]  = fmaf(w, h0.x, acc[0]);  acc[1]  = fmaf(w, h0.y, acc[1]);
            acc[2]  = fmaf(w, h0.z, acc[2]);  acc[3]  = fmaf(w, h0.w, acc[3]);
            acc[4]  = fmaf(w, h1.x, acc[4]);  acc[5]  = fmaf(w, h1.y, acc[5]);
            acc[6]  = fmaf(w, h1.z, acc[6]);  acc[7]  = fmaf(w, h1.w, acc[7]);
            acc[8]  = fmaf(w, h2.x, acc[8]);  acc[9]  = fmaf(w, h2.y, acc[9]);
            acc[10] = fmaf(w, h2.z, acc[10]); acc[11] = fmaf(w, h2.w, acc[11]);
            acc[12] = fmaf(w, h3.x, acc[12]); acc[13] = fmaf(w, h3.y, acc[13]);
            acc[14] = fmaf(w, h3.z, acc[14]); acc[15] = fmaf(w, h3.w, acc[15]);
        }

        // store raw pre-activation (for LN stats)
        float4* orow = (float4*)(aout + o * 36 + pbase);
        orow[0] = make_float4(acc[0],  acc[1],  acc[2],  acc[3]);
        orow[1] = make_float4(acc[4],  acc[5],  acc[6],  acc[7]);
        orow[2] = make_float4(acc[8],  acc[9],  acc[10], acc[11]);
        orow[3] = make_float4(acc[12], acc[13], acc[14], acc[15]);
        __syncthreads();

        // LN stats: warp wrp -> positions wrp*4 .. wrp*4+3
#pragma unroll
        for (int pp = 0; pp < 4; pp++) {
            int p = wrp * 4 + pp;
            float s = 0.f, s2 = 0.f;
#pragma unroll
            for (int k = 0; k < 4; k++) {
                float v = aout[(lane + k * 32) * 36 + p];
                s += v; s2 = fmaf(v, v, s2);
            }
#pragma unroll
            for (int off = 16; off > 0; off >>= 1) {
                s  += __shfl_xor_sync(0xffffffffu, s,  off);
                s2 += __shfl_xor_sync(0xffffffffu, s2, off);
            }
            if (lane == 0) {
                float mu  = s * (1.f / 128.f);
                float var = fmaf(s2, 1.f / 128.f, -mu * mu);
                statS[2 * p]     = mu;
                statS[2 * p + 1] = rsqrtf(var + 1e-5f);
            }
        }
        __syncthreads();

        // normalize + affine + LeakyReLU (from registers)
        float g = lngS[o], bb = lnbS[o];
#pragma unroll
        for (int p = 0; p < 16; p++) {
            float mu = statS[2 * (pbase + p)];
            float rs = statS[2 * (pbase + p) + 1];
            float v  = fmaf((acc[p] - mu) * rs, g, bb);
            acc[p] = fmaxf(v, 0.01f * v);
        }
        orow[0] = make_float4(acc[0],  acc[1],  acc[2],  acc[3]);
        orow[1] = make_float4(acc[4],  acc[5],  acc[6],  acc[7]);
        orow[2] = make_float4(acc[8],  acc[9],  acc[10], acc[11]);
        orow[3] = make_float4(acc[12], acc[13], acc[14], acc[15]);

        float* tsw = ain; ain = aout; aout = tsw;
    }

    // final layer: 128 -> 256, write g_film
    __syncthreads();
    for (int i = tid; i < 256 * 128; i += 256) {
        int oo = i >> 7, cc = i & 127;
        wbuf[cc * 257 + oo] = W3[i];
    }
    __syncthreads();
    {
        float acc[32];
        float bo = B3[tid];
#pragma unroll
        for (int p = 0; p < 32; p++) acc[p] = bo;
#pragma unroll 2
        for (int c = 0; c < 128; c++) {
            float w = wbuf[c * 257 + tid];
            const float4* hr = (const float4*)(ain + c * 36);
#pragma unroll
            for (int q = 0; q < 8; q++) {
                float4 h = hr[q];
                acc[q * 4 + 0] = fmaf(w, h.x, acc[q * 4 + 0]);
                acc[q * 4 + 1] = fmaf(w, h.y, acc[q * 4 + 1]);
                acc[q * 4 + 2] = fmaf(w, h.z, acc[q * 4 + 2]);
                acc[q * 4 + 3] = fmaf(w, h.w, acc[q * 4 + 3]);
            }
        }
        float4* dst = (float4*)(g_film + (b * 256 + tid) * 1024 + tc0);
#pragma unroll
        for (int q = 0; q < 8; q++)
            dst[q] = make_float4(acc[q * 4], acc[q * 4 + 1], acc[q * 4 + 2], acc[q * 4 + 3]);
    }
}

// ===========================================================================
// Kernel 2: FiLM interp + per-channel 1->16->16->1 sine MLP + mixer + x4 up.
// Persistent: 1 block/SM, 512 threads (16 warps). Warp owns 4 channels.
// Lane processes a packed pair of adjacent samples (t, t+1); chunk = 64 t.
// ===========================================================================
__global__ __launch_bounds__(512, 1) void newt_kernel(
    const float* __restrict__ ex, const float* __restrict__ iscale,
    const float* __restrict__ w0g, const float* __restrict__ b0g,
    const float* __restrict__ w1g, const float* __restrict__ b1g,
    const float* __restrict__ w2g, const float* __restrict__ b2g,
    const float* __restrict__ mixwg, const float* __restrict__ mixbg,
    float* __restrict__ outp)
{
    extern __shared__ float sm2[];
    float* sw1 = sm2;                  // 32768: w1[c][o][i] duplicated (w,w)
    float* sw0 = sm2 + 32768;          // 2048
    float* sb0 = sm2 + 34816;          // 2048
    float* sb1 = sm2 + 36864;          // 2048
    float* sw2 = sm2 + 38912;          // 2048
    float* sb2 = sm2 + 40960;          // 128
    float* smx = sm2 + 41088;          // 128
    float* sis = sm2 + 41216;          // 128
    ull*   red = (ull*)(sm2 + 41344);  // 512 ull

    const int tid = threadIdx.x;

    // stage weights, duplicated into (w,w) pairs
    for (int i = tid; i < 64 * 256; i += 512) {
        float w = w1g[i]; sw1[2 * i] = w; sw1[2 * i + 1] = w;
    }
    for (int i = tid; i < 1024; i += 512) {
        float a = w0g[i]; sw0[2 * i] = a; sw0[2 * i + 1] = a;
        float b = b0g[i]; sb0[2 * i] = b; sb0[2 * i + 1] = b;
        float c = b1g[i]; sb1[2 * i] = c; sb1[2 * i + 1] = c;
        float d = w2g[i]; sw2[2 * i] = d; sw2[2 * i + 1] = d;
    }
    if (tid < 64) {
        float a = b2g[tid];   sb2[2 * tid] = a; sb2[2 * tid + 1] = a;
        float b = mixwg[tid]; smx[2 * tid] = b; smx[2 * tid + 1] = b;
        float c = iscale[tid]; sis[2 * tid] = c; sis[2 * tid + 1] = c;
    }
    __syncthreads();

    const int lane = tid & 31;
    const int wid  = tid >> 5;
    const int side = lane >> 4;                  // dt >= 32
    // interp fraction per lane (relative position within 64-t chunk)
    float rp0 = (2 * lane) * 0.015625f + 0.0078125f - 0.5f;
    float rp1 = rp0 + 0.015625f;
    float add = side ? 0.0f : 1.0f;
    const ull fracp = pk2(rp0 + add, rp1 + add);

    // Cody-Waite 2pi reduction constants (packed)
    const ull C_INV = pk2(0.15915494309189535f, 0.15915494309189535f);
    const ull C_MAG = pk2(12582912.0f, 12582912.0f);
    const ull C_NMG = pk2(-12582912.0f, -12582912.0f);
    const ull C_HI  = pk2(-6.2831854820251465f, -6.2831854820251465f);
    const ull C_LO  = pk2(1.7484556e-7f, 1.7484556e-7f);

    for (int task = blockIdx.x; task < 4096; task += gridDim.x) {
        const int b  = task >> 10;
        const int T0 = task & 1023;
        const int t0 = T0 << 6;
        int iA = T0 - 1 + side; if (iA < 0) iA = 0;
        int iB = T0 + side;     if (iB > 1023) iB = 1023;

        ull mixacc = pk2(0.f, 0.f);
#pragma unroll 1
        for (int k = 0; k < 4; k++) {
            const int c = (wid << 2) + k;
            const float* fr = g_film + b * 262144 + c * 1024;
            float fa, fb, dd;
            fa = __ldg(fr + iA);           fb = __ldg(fr + iB);           dd = fb - fa;
            ull gip = ffma2(fracp, pk2(dd, dd), pk2(fa, fa));
            fa = __ldg(fr + 65536 + iA);   fb = __ldg(fr + 65536 + iB);   dd = fb - fa;
            ull bip = ffma2(fracp, pk2(dd, dd), pk2(fa, fa));
            fa = __ldg(fr + 131072 + iA);  fb = __ldg(fr + 131072 + iB);  dd = fb - fa;
            ull gnp = ffma2(fracp, pk2(dd, dd), pk2(fa, fa));
            fa = __ldg(fr + 196608 + iA);  fb = __ldg(fr + 196608 + iB);  dd = fb - fa;
            ull bnp = ffma2(fracp, pk2(dd, dd), pk2(fa, fa));

            float2 e2 = *(const float2*)(ex + ((b << 6) + c) * 65536 + t0 + 2 * lane);
            ull xp = ffma2(gip, pk2(e2.x, e2.y), bip);
            xp = fmul2(xp, *(const ull*)(sis + 2 * c));

            // layer 0: 1 -> 16, sin with CW range reduction
            ull h0[16];
            const ull* w0r = (const ull*)(sw0 + c * 32);
            const ull* b0r = (const ull*)(sb0 + c * 32);
#pragma unroll
            for (int j = 0; j < 16; j++) {
                ull arg = ffma2(xp, w0r[j], b0r[j]);
                ull kk = fadd2(ffma2(arg, C_INV, C_MAG), C_NMG);
                arg = ffma2(kk, C_LO, ffma2(kk, C_HI, arg));
                float lo, hi; upk2(lo, hi, arg);
                h0[j] = pk2(__sinf(lo), __sinf(hi));
            }

            // layer 1 (16x16) fused with layer 2 reduction
            ull yacc = *(const ull*)(sb2 + 2 * c);
            const ull* b1r = (const ull*)(sb1 + c * 32);
            const ull* w2r = (const ull*)(sw2 + c * 32);
#pragma unroll
            for (int o = 0; o < 16; o++) {
                ull acc = b1r[o];
                const ulonglong2* wr = (const ulonglong2*)(sw1 + (c * 256 + o * 16) * 2);
#pragma unroll
                for (int i2 = 0; i2 < 8; i2++) {
                    ulonglong2 wv = wr[i2];
                    acc = ffma2(h0[2 * i2],     wv.x, acc);
                    acc = ffma2(h0[2 * i2 + 1], wv.y, acc);
                }
                float lo, hi; upk2(lo, hi, acc);
                yacc = ffma2(pk2(__sinf(lo), __sinf(hi)), w2r[o], yacc);
            }
            float ylo, yhi; upk2(ylo, yhi, yacc);
            ull op = ffma2(gnp, pk2(__sinf(ylo), __sinf(yhi)), bnp);
            mixacc = ffma2(*(const ull*)(smx + 2 * c), op, mixacc);
        }

        red[(wid << 5) + lane] = mixacc;
        __syncthreads();
        if (tid < 64) {
            const float* rf = (const float*)red;
            float s = __ldg(mixbg);
#pragma unroll
            for (int w = 0; w < 16; w++) s += rf[w * 64 + tid];
            *(float4*)(outp + b * 262144 + ((t0 + tid) << 2)) = make_float4(s, s, s, s);
        }
        __syncthreads();
    }
}

// ===========================================================================
extern "C" void kernel_launch(void* const* d_in, const int* in_sizes, int n_in,
                              void* d_out, int out_size) {
    const float* ex    = (const float*)d_in[0];
    const float* ce    = (const float*)d_in[1];
    const float* w0    = (const float*)d_in[2];
    const float* b0    = (const float*)d_in[3];
    const float* g0    = (const float*)d_in[4];
    const float* be0   = (const float*)d_in[5];
    const float* w1    = (const float*)d_in[6];
    const float* b1    = (const float*)d_in[7];
    const float* g1    = (const float*)d_in[8];
    const float* be1   = (const float*)d_in[9];
    const float* w2    = (const float*)d_in[10];
    const float* b2    = (const float*)d_in[11];
    const float* g2    = (const float*)d_in[12];
    const float* be2   = (const float*)d_in[13];
    const float* w3    = (const float*)d_in[14];
    const float* b3    = (const float*)d_in[15];
    const float* iscl  = (const float*)d_in[16];
    const float* sfw0  = (const float*)d_in[17];
    const float* sfb0  = (const float*)d_in[18];
    const float* sfw1  = (const float*)d_in[19];
    const float* sfb1  = (const float*)d_in[20];
    const float* sfw2  = (const float*)d_in[21];
    const float* sfb2  = (const float*)d_in[22];
    const float* mixw  = (const float*)d_in[23];
    const float* mixb  = (const float*)d_in[24];
    float* out = (float*)d_out;

    const int SM1 = 42688 * 4;   // 170752 B
    const int SM2 = 42368 * 4;   // 169472 B
    cudaFuncSetAttribute(mlp_kernel,  cudaFuncAttributeMaxDynamicSharedMemorySize, SM1);
    cudaFuncSetAttribute(newt_kernel, cudaFuncAttributeMaxDynamicSharedMemorySize, SM2);

    int nsm = 148;
    cudaDeviceGetAttribute(&nsm, cudaDevAttrMultiProcessorCount, 0);
    if (nsm <= 0) nsm = 148;

    mlp_kernel<<<128, 256, SM1>>>(ce, w0, b0, g0, be0, w1, b1, g1, be1,
                                  w2, b2, g2, be2, w3, b3);
    newt_kernel<<<nsm, 512, SM2>>>(ex, iscl, sfw0, sfb0, sfw1, sfb1,
                                   sfw2, sfb2, mixw, mixb, out);
}

// round 7
// speedup vs baseline: 1.1654x; 1.1654x over previous
#include <cuda_runtime.h>

typedef unsigned long long ull;

// film buffer: [b(4)][ch(256)][tc(1024)]
__device__ float g_film[4 * 256 * 1024];

// ---------------- packed f32x2 helpers (sm_103a FFMA2 path) ----------------
__device__ __forceinline__ ull pk2(float lo, float hi) {
    ull r; asm("mov.b64 %0, {%1, %2};" : "=l"(r) : "f"(lo), "f"(hi)); return r;
}
__device__ __forceinline__ void upk2(float& lo, float& hi, ull v) {
    asm("mov.b64 {%0, %1}, %2;" : "=f"(lo), "=f"(hi) : "l"(v));
}
__device__ __forceinline__ ull ffma2(ull a, ull b, ull c) {
    ull d; asm("fma.rn.f32x2 %0, %1, %2, %3;" : "=l"(d) : "l"(a), "l"(b), "l"(c)); return d;
}
__device__ __forceinline__ ull fadd2(ull a, ull b) {
    ull d; asm("add.rn.f32x2 %0, %1, %2;" : "=l"(d) : "l"(a), "l"(b)); return d;
}
__device__ __forceinline__ ull fmul2(ull a, ull b) {
    ull d; asm("mul.rn.f32x2 %0, %1, %2;" : "=l"(d) : "l"(a), "l"(b)); return d;
}

// ===========================================================================
// Kernel 1: control-rate MLP. 128 blocks x 256 threads, 32 positions/block.
// ===========================================================================
__global__ __launch_bounds__(256) void mlp_kernel(
    const float* __restrict__ cein,
    const float* __restrict__ W0, const float* __restrict__ B0,
    const float* __restrict__ G0, const float* __restrict__ Be0,
    const float* __restrict__ W1, const float* __restrict__ B1,
    const float* __restrict__ G1, const float* __restrict__ Be1,
    const float* __restrict__ W2, const float* __restrict__ B2,
    const float* __restrict__ G2, const float* __restrict__ Be2,
    const float* __restrict__ W3, const float* __restrict__ B3)
{
    extern __shared__ float sm1[];
    float* wbuf  = sm1;              // up to 128*257 = 32896 floats
    float* actA  = sm1 + 32896;      // 128 rows x pitch 36
    float* actB  = actA + 4608;
    float* biasS = actB + 4608;      // 256
    float* lngS  = biasS + 256;      // 128
    float* lnbS  = lngS + 128;       // 128
    float* statS = lnbS + 128;       // 64

    const int tid = threadIdx.x;
    const int P0  = blockIdx.x * 32;
    const int b   = P0 >> 10;
    const int tc0 = P0 & 1023;

    // stage input slice actA[c][p] = ce[b][c][tc0+p]
    for (int i = tid; i < 128 * 32; i += 256) {
        int c = i >> 5, p = i & 31;
        actA[c * 36 + p] = cein[(b * 128 + c) * 1024 + tc0 + p];
    }

    const float* Wl[3]  = {W0, W1, W2};
    const float* Bl[3]  = {B0, B1, B2};
    const float* Gl[3]  = {G0, G1, G2};
    const float* Bel[3] = {Be0, Be1, Be2};

    float* ain  = actA;
    float* aout = actB;

    const int o     = tid & 127;
    const int half  = tid >> 7;
    const int pbase = half * 16;
    const int wrp   = tid >> 5;
    const int lane  = tid & 31;

    for (int layer = 0; layer < 3; layer++) {
        __syncthreads();
        // stage transposed weight via float4 LDG: wbuf[c*129 + o] = W[o][c]
        const float* W = Wl[layer];
        for (int i = tid; i < 128 * 32; i += 256) {
            int oo = i >> 5, c4 = (i & 31) << 2;
            float4 w = *(const float4*)(W + oo * 128 + c4);
            wbuf[(c4 + 0) * 129 + oo] = w.x;
            wbuf[(c4 + 1) * 129 + oo] = w.y;
            wbuf[(c4 + 2) * 129 + oo] = w.z;
            wbuf[(c4 + 3) * 129 + oo] = w.w;
        }
        if (tid < 128) {
            biasS[tid] = Bl[layer][tid];
            lngS[tid]  = Gl[layer][tid];
            lnbS[tid]  = Bel[layer][tid];
        }
        __syncthreads();

        float acc[16];
        float bo = biasS[o];
#pragma unroll
        for (int p = 0; p < 16; p++) acc[p] = bo;

        const float* arow = ain + pbase;
#pragma unroll 4
        for (int c = 0; c < 128; c++) {
            float w = wbuf[c * 129 + o];
            const float4* hr = (const float4*)(arow + c * 36);
            float4 h0 = hr[0], h1 = hr[1], h2 = hr[2], h3 = hr[3];
            acc[0]  = fmaf(w, h0.x, acc[0]);  acc[1]  = fmaf(w, h0.y, acc[1]);
            acc[2]  = fmaf(w, h0.z, acc[2]);  acc[3]  = fmaf(w, h0.w, acc[3]);
            acc[4]  = fmaf(w, h1.x, acc[4]);  acc[5]  = fmaf(w, h1.y, acc[5]);
            acc[6]  = fmaf(w, h1.z, acc[6]);  acc[7]  = fmaf(w, h1.w, acc[7]);
            acc[8]  = fmaf(w, h2.x, acc[8]);  acc[9]  = fmaf(w, h2.y, acc[9]);
            acc[10] = fmaf(w, h2.z, acc[10]); acc[11] = fmaf(w, h2.w, acc[11]);
            acc[12] = fmaf(w, h3.x, acc[12]); acc[13] = fmaf(w, h3.y, acc[13]);
            acc[14] = fmaf(w, h3.z, acc[14]); acc[15] = fmaf(w, h3.w, acc[15]);
        }

        // store raw pre-activation (for LN stats)
        float4* orow = (float4*)(aout + o * 36 + pbase);
        orow[0] = make_float4(acc[0],  acc[1],  acc[2],  acc[3]);
        orow[1] = make_float4(acc[4],  acc[5],  acc[6],  acc[7]);
        orow[2] = make_float4(acc[8],  acc[9],  acc[10], acc[11]);
        orow[3] = make_float4(acc[12], acc[13], acc[14], acc[15]);
        __syncthreads();

        // LN stats: warp wrp -> positions wrp*4 .. wrp*4+3
#pragma unroll
        for (int pp = 0; pp < 4; pp++) {
            int p = wrp * 4 + pp;
            float s = 0.f, s2 = 0.f;
#pragma unroll
            for (int k = 0; k < 4; k++) {
                float v = aout[(lane + k * 32) * 36 + p];
                s += v; s2 = fmaf(v, v, s2);
            }
#pragma unroll
            for (int off = 16; off > 0; off >>= 1) {
                s  += __shfl_xor_sync(0xffffffffu, s,  off);
                s2 += __shfl_xor_sync(0xffffffffu, s2, off);
            }
            if (lane == 0) {
                float mu  = s * (1.f / 128.f);
                float var = fmaf(s2, 1.f / 128.f, -mu * mu);
                statS[2 * p]     = mu;
                statS[2 * p + 1] = rsqrtf(var + 1e-5f);
            }
        }
        __syncthreads();

        // normalize + affine + LeakyReLU (from registers)
        float g = lngS[o], bb = lnbS[o];
#pragma unroll
        for (int p = 0; p < 16; p++) {
            float mu = statS[2 * (pbase + p)];
            float rs = statS[2 * (pbase + p) + 1];
            float v  = fmaf((acc[p] - mu) * rs, g, bb);
            acc[p] = fmaxf(v, 0.01f * v);
        }
        orow[0] = make_float4(acc[0],  acc[1],  acc[2],  acc[3]);
        orow[1] = make_float4(acc[4],  acc[5],  acc[6],  acc[7]);
        orow[2] = make_float4(acc[8],  acc[9],  acc[10], acc[11]);
        orow[3] = make_float4(acc[12], acc[13], acc[14], acc[15]);

        float* tsw = ain; ain = aout; aout = tsw;
    }

    // final layer: 128 -> 256, write g_film
    __syncthreads();
    for (int i = tid; i < 256 * 32; i += 256) {
        int oo = i >> 5, c4 = (i & 31) << 2;
        float4 w = *(const float4*)(W3 + oo * 128 + c4);
        wbuf[(c4 + 0) * 257 + oo] = w.x;
        wbuf[(c4 + 1) * 257 + oo] = w.y;
        wbuf[(c4 + 2) * 257 + oo] = w.z;
        wbuf[(c4 + 3) * 257 + oo] = w.w;
    }
    __syncthreads();
    {
        float acc[32];
        float bo = B3[tid];
#pragma unroll
        for (int p = 0; p < 32; p++) acc[p] = bo;
#pragma unroll 2
        for (int c = 0; c < 128; c++) {
            float w = wbuf[c * 257 + tid];
            const float4* hr = (const float4*)(ain + c * 36);
#pragma unroll
            for (int q = 0; q < 8; q++) {
                float4 h = hr[q];
                acc[q * 4 + 0] = fmaf(w, h.x, acc[q * 4 + 0]);
                acc[q * 4 + 1] = fmaf(w, h.y, acc[q * 4 + 1]);
                acc[q * 4 + 2] = fmaf(w, h.z, acc[q * 4 + 2]);
                acc[q * 4 + 3] = fmaf(w, h.w, acc[q * 4 + 3]);
            }
        }
        float4* dst = (float4*)(g_film + (b * 256 + tid) * 1024 + tc0);
#pragma unroll
        for (int q = 0; q < 8; q++)
            dst[q] = make_float4(acc[q * 4], acc[q * 4 + 1], acc[q * 4 + 2], acc[q * 4 + 3]);
    }
}

// ===========================================================================
// Kernel 2: FiLM interp + per-channel 1->16->16->1 sine MLP + mixer + x4 up.
// Persistent: 1 block/SM, 512 threads (16 warps). Warp owns 4 channels.
// Each lane processes TWO packed sample-pairs (4 samples) sharing every
// weight LDS -> halved L1 pressure, 4 independent FFMA2 chains for ILP.
// Task = 128 consecutive samples of one batch element.
// ===========================================================================
__global__ __launch_bounds__(512, 1) void newt_kernel(
    const float* __restrict__ ex, const float* __restrict__ iscale,
    const float* __restrict__ w0g, const float* __restrict__ b0g,
    const float* __restrict__ w1g, const float* __restrict__ b1g,
    const float* __restrict__ w2g, const float* __restrict__ b2g,
    const float* __restrict__ mixwg, const float* __restrict__ mixbg,
    float* __restrict__ outp)
{
    extern __shared__ float sm2[];
    float* sw1   = sm2;                    // 32768: w1[c][o][i] dup (w,w)
    float* sw0   = sm2 + 32768;            // 2048 dup
    float* sb0   = sm2 + 34816;            // 2048 dup
    float* sb1w2 = sm2 + 36864;            // 4096: per (c,o): {b1,b1,w2,w2}
    float* sb2   = sm2 + 40960;            // 128 dup
    float* smx   = sm2 + 41088;            // 128 dup
    float* sis   = sm2 + 41216;            // 128 dup
    ull*   red   = (ull*)(sm2 + 41344);    // 1024 ull (A then B)

    const int tid = threadIdx.x;

    // stage weights (duplicated (w,w) pairs)
    for (int i = tid; i < 64 * 256; i += 512) {
        float w = w1g[i]; sw1[2 * i] = w; sw1[2 * i + 1] = w;
    }
    for (int i = tid; i < 1024; i += 512) {
        float a = w0g[i]; sw0[2 * i] = a; sw0[2 * i + 1] = a;
        float b = b0g[i]; sb0[2 * i] = b; sb0[2 * i + 1] = b;
        float c = b1g[i]; sb1w2[4 * i + 0] = c; sb1w2[4 * i + 1] = c;
        float d = w2g[i]; sb1w2[4 * i + 2] = d; sb1w2[4 * i + 3] = d;
    }
    if (tid < 64) {
        float a = b2g[tid];    sb2[2 * tid] = a; sb2[2 * tid + 1] = a;
        float b = mixwg[tid];  smx[2 * tid] = b; smx[2 * tid + 1] = b;
        float c = iscale[tid]; sis[2 * tid] = c; sis[2 * tid + 1] = c;
    }
    __syncthreads();

    const int lane = tid & 31;
    const int wid  = tid >> 5;
    const int side = lane >> 4;
    // identical interp fraction for both pairs (see derivation)
    float f0 = (2 * lane) * 0.015625f + 0.0078125f + 0.5f - (float)side;
    const ull fracp = pk2(f0, f0 + 0.015625f);
    const ull ZZ = pk2(0.f, 0.f);

    // Cody-Waite 2pi reduction constants (packed)
    const ull C_INV = pk2(0.15915494309189535f, 0.15915494309189535f);
    const ull C_MAG = pk2(12582912.0f, 12582912.0f);
    const ull C_NMG = pk2(-12582912.0f, -12582912.0f);
    const ull C_HI  = pk2(-6.2831854820251465f, -6.2831854820251465f);
    const ull C_LO  = pk2(1.7484556e-7f, 1.7484556e-7f);

    for (int task = blockIdx.x; task < 2048; task += gridDim.x) {
        const int b  = task >> 9;
        const int tt = task & 511;
        const int t0 = tt << 7;
        const int Tc = tt << 1;
        int i0 = Tc - 1 + side; if (i0 < 0) i0 = 0;
        const int i1 = Tc + side;
        int i2 = Tc + 1 + side; if (i2 > 1023) i2 = 1023;

        ull mixA = ZZ, mixB = ZZ;
#pragma unroll 1
        for (int k = 0; k < 4; k++) {
            const int c = (wid << 2) + k;
            const float* fr = g_film + b * 262144 + c * 1024;

            float ga = __ldg(fr + i0), gb = __ldg(fr + i1), gc = __ldg(fr + i2);
            float ba = __ldg(fr + 65536 + i0), bb = __ldg(fr + 65536 + i1),
                  bc = __ldg(fr + 65536 + i2);
            const float* exr = ex + (((b << 6) + c) << 16) + t0 + 2 * lane;
            float2 eA = *(const float2*)(exr);
            float2 eB = *(const float2*)(exr + 64);

            ull giA = ffma2(fracp, pk2(gb - ga, gb - ga), pk2(ga, ga));
            ull giB = ffma2(fracp, pk2(gc - gb, gc - gb), pk2(gb, gb));
            ull biA = ffma2(fracp, pk2(bb - ba, bb - ba), pk2(ba, ba));
            ull biB = ffma2(fracp, pk2(bc - bb, bc - bb), pk2(bb, bb));

            ull isc = *(const ull*)(sis + 2 * c);
            ull xA = fmul2(ffma2(giA, pk2(eA.x, eA.y), biA), isc);
            ull xB = fmul2(ffma2(giB, pk2(eB.x, eB.y), biB), isc);

            // layer 0: 1 -> 16, sin with CW range reduction (both pairs)
            ull h0a[16], h0b[16];
            const ull* w0r = (const ull*)(sw0 + c * 32);
            const ull* b0r = (const ull*)(sb0 + c * 32);
#pragma unroll
            for (int j = 0; j < 16; j++) {
                ull wj = w0r[j], bj = b0r[j];
                ull aA = ffma2(xA, wj, bj);
                ull kA = fadd2(ffma2(aA, C_INV, C_MAG), C_NMG);
                aA = ffma2(kA, C_LO, ffma2(kA, C_HI, aA));
                float lo, hi; upk2(lo, hi, aA);
                h0a[j] = pk2(__sinf(lo), __sinf(hi));
                ull aB = ffma2(xB, wj, bj);
                ull kB = fadd2(ffma2(aB, C_INV, C_MAG), C_NMG);
                aB = ffma2(kB, C_LO, ffma2(kB, C_HI, aB));
                upk2(lo, hi, aB);
                h0b[j] = pk2(__sinf(lo), __sinf(hi));
            }

            // layer 1 (16x16) fused with layer 2 reduction; shared weight LDS
            ull yA = *(const ull*)(sb2 + 2 * c);
            ull yB = yA;
            const ulonglong2* wr  = (const ulonglong2*)(sw1 + c * 512);
            const ulonglong2* bwp = (const ulonglong2*)(sb1w2) + c * 16;
#pragma unroll
            for (int o = 0; o < 16; o++) {
                ulonglong2 bw = bwp[o];
                ull aA0 = bw.x, aA1 = ZZ, aB0 = bw.x, aB1 = ZZ;
#pragma unroll
                for (int i = 0; i < 8; i++) {
                    ulonglong2 wv = wr[o * 8 + i];
                    aA0 = ffma2(h0a[2 * i],     wv.x, aA0);
                    aA1 = ffma2(h0a[2 * i + 1], wv.y, aA1);
                    aB0 = ffma2(h0b[2 * i],     wv.x, aB0);
                    aB1 = ffma2(h0b[2 * i + 1], wv.y, aB1);
                }
                ull sA = fadd2(aA0, aA1);
                ull sB = fadd2(aB0, aB1);
                float lo, hi;
                upk2(lo, hi, sA);
                yA = ffma2(pk2(__sinf(lo), __sinf(hi)), bw.y, yA);
                upk2(lo, hi, sB);
                yB = ffma2(pk2(__sinf(lo), __sinf(hi)), bw.y, yB);
            }

            // deferred gamma_n / beta_n (L1-resident) + final FiLM + mix
            float na = __ldg(fr + 131072 + i0), nb = __ldg(fr + 131072 + i1),
                  nc = __ldg(fr + 131072 + i2);
            float pa = __ldg(fr + 196608 + i0), pb = __ldg(fr + 196608 + i1),
                  pc = __ldg(fr + 196608 + i2);
            ull gnA = ffma2(fracp, pk2(nb - na, nb - na), pk2(na, na));
            ull gnB = ffma2(fracp, pk2(nc - nb, nc - nb), pk2(nb, nb));
            ull bnA = ffma2(fracp, pk2(pb - pa, pb - pa), pk2(pa, pa));
            ull bnB = ffma2(fracp, pk2(pc - pb, pc - pb), pk2(pb, pb));

            float lo, hi;
            upk2(lo, hi, yA);
            ull oA = ffma2(gnA, pk2(__sinf(lo), __sinf(hi)), bnA);
            upk2(lo, hi, yB);
            ull oB = ffma2(gnB, pk2(__sinf(lo), __sinf(hi)), bnB);

            ull mw = *(const ull*)(smx + 2 * c);
            mixA = ffma2(mw, oA, mixA);
            mixB = ffma2(mw, oB, mixB);
        }

        red[(wid << 5) + lane] = mixA;
        red[512 + (wid << 5) + lane] = mixB;
        __syncthreads();
        if (tid < 128) {
            int grp = tid >> 6, j = tid & 63;
            const float* rf = (const float*)(red + (grp << 9));
            float s = __ldg(mixbg);
#pragma unroll
            for (int w = 0; w < 16; w++) s += rf[(w << 6) + j];
            int t = t0 + (grp << 6) + j;
            *(float4*)(outp + (b << 18) + (t << 2)) = make_float4(s, s, s, s);
        }
        __syncthreads();
    }
}

// ===========================================================================
extern "C" void kernel_launch(void* const* d_in, const int* in_sizes, int n_in,
                              void* d_out, int out_size) {
    const float* ex    = (const float*)d_in[0];
    const float* ce    = (const float*)d_in[1];
    const float* w0    = (const float*)d_in[2];
    const float* b0    = (const float*)d_in[3];
    const float* g0    = (const float*)d_in[4];
    const float* be0   = (const float*)d_in[5];
    const float* w1    = (const float*)d_in[6];
    const float* b1    = (const float*)d_in[7];
    const float* g1    = (const float*)d_in[8];
    const float* be1   = (const float*)d_in[9];
    const float* w2    = (const float*)d_in[10];
    const float* b2    = (const float*)d_in[11];
    const float* g2    = (const float*)d_in[12];
    const float* be2   = (const float*)d_in[13];
    const float* w3    = (const float*)d_in[14];
    const float* b3    = (const float*)d_in[15];
    const float* iscl  = (const float*)d_in[16];
    const float* sfw0  = (const float*)d_in[17];
    const float* sfb0  = (const float*)d_in[18];
    const float* sfw1  = (const float*)d_in[19];
    const float* sfb1  = (const float*)d_in[20];
    const float* sfw2  = (const float*)d_in[21];
    const float* sfb2  = (const float*)d_in[22];
    const float* mixw  = (const float*)d_in[23];
    const float* mixb  = (const float*)d_in[24];
    float* out = (float*)d_out;

    const int SM1 = 42688 * 4;   // 170752 B
    const int SM2 = 43392 * 4;   // 173568 B
    cudaFuncSetAttribute(mlp_kernel,  cudaFuncAttributeMaxDynamicSharedMemorySize, SM1);
    cudaFuncSetAttribute(newt_kernel, cudaFuncAttributeMaxDynamicSharedMemorySize, SM2);

    int nsm = 148;
    cudaDeviceGetAttribute(&nsm, cudaDevAttrMultiProcessorCount, 0);
    if (nsm <= 0) nsm = 148;

    mlp_kernel<<<128, 256, SM1>>>(ce, w0, b0, g0, be0, w1, b1, g1, be1,
                                  w2, b2, g2, be2, w3, b3);
    newt_kernel<<<nsm, 512, SM2>>>(ex, iscl, sfw0, sfb0, sfw1, sfb1,
                                   sfw2, sfb2, mixw, mixb, out);
}